// round 2
// baseline (speedup 1.0000x reference)
#include <cuda_runtime.h>

#define T_LEN 2048

__device__ __forceinline__ float tanh_fast(float x) {
    float y;
    asm("tanh.approx.f32 %0, %1;" : "=f"(y) : "f"(x));
    return y;
}

// All state carried in the x10 domain: WU = 10*wu, etc. Inputs PET10 = 10*pet,
// P10 = 10*p. heaviside(a-b) args are then direct subtractions (arg10 = A - B).
// Clips at +-1e5 dropped: |p - et...| <= O(max state) <= O(T) ~ 2e3 << 1e5,
// since p,pet in [0,1] and all et terms are smooth blends of {state, pet}-scale
// quantities -> the clip is an exact no-op on reachable values.
struct XajStep {
    float WU, WL, WD;

    __device__ __forceinline__ float step(float pet10, float p10, float p_raw,
                                          float invW10, float c2, float b2,
                                          float halfF) {
        // ---- et1 = h1*pet + (1-h1)*wu,  h1 = H(wu - pet) ----
        const float t1  = tanh_fast(WU - pet10);
        const float ET1 = fmaf(t1, 0.5f * (pet10 - WU), 0.5f * (pet10 + WU));

        // ---- rem = H(pet - et1) * (pet - et1) ----
        const float Z   = pet10 - ET1;
        const float tr  = tanh_fast(Z);
        const float hZ  = 0.5f * Z;
        const float REM = fmaf(tr, hZ, hZ);

        // ---- et22 = h2*wl + (1-h2)*rem ; et2 = H(rem)*et22 ----
        const float t2   = tanh_fast(REM - WL);
        const float t3   = tanh_fast(REM);
        const float ET22 = fmaf(t2, 0.5f * (WL - REM), 0.5f * (WL + REM));
        const float hE22 = 0.5f * ET22;
        const float ET2  = fmaf(t3, hE22, hE22);

        // ---- x = rem - et2 ; et33 = h4*wd + (1-h4)*x ; et3 = H(x)*et33 ----
        const float X    = REM - ET2;
        const float t4   = tanh_fast(X - WD);
        const float t5   = tanh_fast(X);
        const float ET33 = fmaf(t4, 0.5f * (WD - X), 0.5f * (WD + X));
        const float hE33 = 0.5f * ET33;
        const float ET3  = fmaf(t5, hE33, hE33);

        // ---- state update (trajectory stores the NEW state) ----
        const float D1 = p10 - ET1;
        WU += D1;
        const float D2 = D1 - ET2;
        WL += D2;
        const float D3 = D2 - ET3;
        WD += D3;

        // ---- runoff + partition + routing (off the carried chain) ----
        // reference calls runoff_production(wu, wd, wl, ...): u uses wu, v uses wd
        const float u  = WU * invW10;   // = wu / W
        const float v  = WD * invW10;   // = wd / W
        const float s  = fmaf(c2, u * u, b2 * (v * v));
        const float dd = p_raw - s;
        const float tq = tanh_fast(10.0f * dd);
        const float qh = halfF * dd;
        return fmaf(tq, qh, qh);        // F * H(p-s) * (p-s)
    }
};

__global__ void __launch_bounds__(32, 1) xaj_kernel(
    const float* __restrict__ inputs,
    const float* __restrict__ pwum, const float* __restrict__ pwlm,
    const float* __restrict__ pwdm, const float* __restrict__ pc,
    const float* __restrict__ pb,  const float* __restrict__ pk1,
    const float* __restrict__ pk2, const float* __restrict__ pk3,
    float* __restrict__ out, int B)
{
    const int b = blockIdx.x * blockDim.x + threadIdx.x;
    if (b >= B) return;

    // scalar parameter preprocessing (reference swaps wlm/wdm in the call:
    // runoff_production(wu, wd, wl, p, wum, wdm, wlm, b, c))
    const float wum_p = pwum[0] * 19.9f + 0.1f;
    const float wlm_p = pwdm[0] * 30.0f + 60.0f;
    const float wdm_p = pwlm[0] * 60.0f + 60.0f;
    const float W     = wum_p + wlm_p + wdm_p;
    const float invW10 = 0.1f / W;          // converts x10-state to wu/W
    const float c2 = pc[0] * 0.19f + 0.01f;
    const float b2 = pb[0] * 0.30f + 0.10f;
    const float k1 = pk1[0] * 0.69f + 0.01f;
    const float k2 = pk2[0] * 0.69f + 0.01f;
    const float k3 = pk3[0] * 0.89f + 0.01f;
    const float F = k1 + 0.5f * k2 * (1.0f - k1)
                  + 0.25f * k3 * (1.0f - k2) * (1.0f - k1);
    const float halfF = 0.5f * F;

    const float4* __restrict__ in4 =
        reinterpret_cast<const float4*>(inputs + (size_t)b * (T_LEN * 3));
    float4* __restrict__ out4 =
        reinterpret_cast<float4*>(out + (size_t)b * T_LEN);

    XajStep S;
    S.WU = 0.0f; S.WL = 0.0f; S.WD = 0.0f;

    const int NG = T_LEN / 4;   // groups of 4 timesteps (3 float4s in, 1 out)
    float4 A = in4[0], Bv = in4[1], C = in4[2];

    #pragma unroll 2
    for (int g = 0; g < NG; ++g) {
        const int gn = (g + 1 < NG) ? (g + 1) : g;
        const float4 nA = in4[gn * 3 + 0];
        const float4 nB = in4[gn * 3 + 1];
        const float4 nC = in4[gn * 3 + 2];

        // (B,T,3): pet = ch0, p = ch2
        // step 0: pet=A.x p=A.z | step 1: pet=A.w p=Bv.y
        // step 2: pet=Bv.z p=C.x | step 3: pet=C.y p=C.w
        float4 q;
        q.x = S.step(10.0f * A.x,  10.0f * A.z,  A.z,  invW10, c2, b2, halfF);
        q.y = S.step(10.0f * A.w,  10.0f * Bv.y, Bv.y, invW10, c2, b2, halfF);
        q.z = S.step(10.0f * Bv.z, 10.0f * C.x,  C.x,  invW10, c2, b2, halfF);
        q.w = S.step(10.0f * C.y,  10.0f * C.w,  C.w,  invW10, c2, b2, halfF);

        out4[g] = q;

        A = nA; Bv = nB; C = nC;
    }
}

extern "C" void kernel_launch(void* const* d_in, const int* in_sizes, int n_in,
                              void* d_out, int out_size) {
    const float* inputs = (const float*)d_in[0];
    const float* wum = (const float*)d_in[1];
    const float* wlm = (const float*)d_in[2];
    const float* wdm = (const float*)d_in[3];
    const float* c   = (const float*)d_in[4];
    const float* bb  = (const float*)d_in[5];
    const float* k1  = (const float*)d_in[6];
    const float* k2  = (const float*)d_in[7];
    const float* k3  = (const float*)d_in[8];
    float* out = (float*)d_out;

    const int B = in_sizes[0] / (T_LEN * 3);

    dim3 block(32);
    dim3 grid((B + 31) / 32);
    xaj_kernel<<<grid, block>>>(inputs, wum, wlm, wdm, c, bb, k1, k2, k3, out, B);
}